// round 4
// baseline (speedup 1.0000x reference)
#include <cuda_runtime.h>
#include <math.h>

#define NVOX 120000
#define EPSV 1e-5f

// ---------------- scratch (no dynamic alloc allowed) ----------------
__device__ float g_bufA[NVOX * 64];
__device__ float g_bufB[NVOX * 64];
__device__ float g_bufC[NVOX * 64];
__device__ float g_bufD[NVOX * 64];
__device__ float g_sum[7 * 64];
__device__ float g_sq [7 * 64];
__device__ float g_sc [7 * 64];
__device__ float g_sh [7 * 64];

// ---------------- packed f32x2 helpers ----------------
__device__ __forceinline__ unsigned long long pack2same(float v) {
    unsigned long long r;
    asm("mov.b64 %0, {%1, %1};" : "=l"(r) : "f"(v));
    return r;
}
__device__ __forceinline__ void unpack2(float& lo, float& hi, unsigned long long a) {
    asm("mov.b64 {%0, %1}, %2;" : "=f"(lo), "=f"(hi) : "l"(a));
}
__device__ __forceinline__ void ffma2(unsigned long long& d, unsigned long long a, unsigned long long b) {
    asm("fma.rn.f32x2 %0, %1, %2, %0;" : "+l"(d) : "l"(a), "l"(b));
}

template <int COUT>
__device__ __forceinline__ void mac_row(unsigned long long* acc, float v, const float* w) {
    unsigned long long vv = pack2same(v);
    const ulonglong2* w2 = reinterpret_cast<const ulonglong2*>(w);
#pragma unroll
    for (int q = 0; q < COUT / 4; q++) {
        ulonglong2 ww = w2[q];
        ffma2(acc[2 * q + 0], vv, ww.x);
        ffma2(acc[2 * q + 1], vv, ww.y);
    }
}

// ---------------- submanifold conv: out = lrelu( sum_k gather_k(in)@W_k ) ----------------
// Optional per-input-channel affine (BN of the previous stage) applied only to
// VALID gathered rows — this exactly matches the reference's zero-pad row.
template <int CIN, int COUT, bool AFFINE>
__global__ void conv_kernel(const float* __restrict__ in, const int* __restrict__ nbr,
                            const float* __restrict__ W,
                            const float* __restrict__ sc, const float* __restrict__ sh,
                            float* __restrict__ out, int n) {
    extern __shared__ __align__(16) float smem[];
    float* ws  = smem;                    // 9*CIN*COUT
    float* csc = ws + 9 * CIN * COUT;     // CIN
    float* csh = csc + CIN;               // CIN
    const int tid = threadIdx.x;
    for (int i = tid; i < 9 * CIN * COUT; i += blockDim.x) ws[i] = W[i];
    if (AFFINE) {
        for (int i = tid; i < CIN; i += blockDim.x) { csc[i] = sc[i]; csh[i] = sh[i]; }
    }
    __syncthreads();

    const int row = blockIdx.x * blockDim.x + tid;
    if (row >= n) return;

    unsigned long long acc[COUT / 2];
#pragma unroll
    for (int i = 0; i < COUT / 2; i++) acc[i] = 0ull;

    const int* nb = nbr + (size_t)row * 9;
#pragma unroll
    for (int k = 0; k < 9; k++) {
        const int j = nb[k];
        if (j >= n) continue;   // missing neighbor -> zero contribution
        const float4* xr = reinterpret_cast<const float4*>(in + (size_t)j * CIN);
        const float* wk = ws + k * CIN * COUT;
#pragma unroll
        for (int c4 = 0; c4 < CIN / 4; c4++) {
            float4 v = xr[c4];
            if (AFFINE) {
                v.x = fmaf(v.x, csc[4 * c4 + 0], csh[4 * c4 + 0]);
                v.y = fmaf(v.y, csc[4 * c4 + 1], csh[4 * c4 + 1]);
                v.z = fmaf(v.z, csc[4 * c4 + 2], csh[4 * c4 + 2]);
                v.w = fmaf(v.w, csc[4 * c4 + 3], csh[4 * c4 + 3]);
            }
            const float* w0 = wk + (4 * c4) * COUT;
            mac_row<COUT>(acc, v.x, w0);
            mac_row<COUT>(acc, v.y, w0 + COUT);
            mac_row<COUT>(acc, v.z, w0 + 2 * COUT);
            mac_row<COUT>(acc, v.w, w0 + 3 * COUT);
        }
    }

    float* o = out + (size_t)row * COUT;
#pragma unroll
    for (int i = 0; i < COUT / 2; i++) {
        float lo, hi;
        unpack2(lo, hi, acc[i]);
        lo = lo > 0.f ? lo : 0.01f * lo;   // leaky relu, slope 0.01
        hi = hi > 0.f ? hi : 0.01f * hi;
        reinterpret_cast<float2*>(o)[i] = make_float2(lo, hi);
    }
}

// ---------------- per-channel sum / sumsq over [n, C] ----------------
template <int C>
__global__ void stats_kernel(const float* __restrict__ d, int n,
                             float* __restrict__ sum, float* __restrict__ sq) {
    __shared__ float ss[512];
    __shared__ float qq[512];
    const int tid = threadIdx.x;
    const int col = tid % C;
    const int rl  = tid / C;
    const int rpb = blockDim.x / C;
    float s = 0.f, q = 0.f;
    for (int r = blockIdx.x * rpb + rl; r < n; r += gridDim.x * rpb) {
        float v = d[(size_t)r * C + col];
        s += v; q += v * v;
    }
    ss[tid] = s; qq[tid] = q;
    __syncthreads();
    for (int off = blockDim.x / 2; off >= C; off >>= 1) {
        if (tid < off) { ss[tid] += ss[tid + off]; qq[tid] += qq[tid + off]; }
        __syncthreads();
    }
    if (tid < C) {
        atomicAdd(sum + tid, ss[tid]);
        atomicAdd(sq + tid, qq[tid]);
    }
}

// ---------------- BN finalize: scale = g/sqrt(var+eps), shift = b - mean*scale ----------------
__global__ void bnfin_kernel(const float* __restrict__ sum, const float* __restrict__ sq,
                             const float* __restrict__ g, const float* __restrict__ b,
                             float* __restrict__ scale, float* __restrict__ shift,
                             int n, int C) {
    int i = threadIdx.x;
    if (i >= C) return;
    float inv_n = 1.0f / (float)n;
    float m   = sum[i] * inv_n;
    float var = sq[i] * inv_n - m * m;   // biased variance (jnp.var default)
    float s   = g[i] / sqrtf(var + EPSV);
    scale[i] = s;
    shift[i] = b[i] - m * s;
}

// ---------------- out = aff(a) + aff(b) elementwise ----------------
template <int C>
__global__ void combine_kernel(const float* __restrict__ a, const float* __restrict__ sa, const float* __restrict__ ha,
                               const float* __restrict__ b, const float* __restrict__ sb, const float* __restrict__ hb,
                               float* __restrict__ o, int total) {
    int i = blockIdx.x * blockDim.x + threadIdx.x;
    if (i >= total) return;
    int c = i & (C - 1);
    o[i] = fmaf(a[i], sa[c], ha[c]) + fmaf(b[i], sb[c], hb[c]);
}

__global__ void zero_stats_kernel(float* __restrict__ sum, float* __restrict__ sq) {
    int i = blockIdx.x * blockDim.x + threadIdx.x;
    if (i < 7 * 64) { sum[i] = 0.f; sq[i] = 0.f; }
}

// ---------------- host launch sequence ----------------
static constexpr size_t smem_for(int cin, int cout) {
    return (size_t)(9 * cin * cout + 2 * cin) * sizeof(float);
}

extern "C" void kernel_launch(void* const* d_in, const int* in_sizes, int n_in,
                              void* d_out, int out_size) {
    const float* x      = (const float*)d_in[0];
    const int*   nbr133 = (const int*)  d_in[1];
    const int*   nbr313 = (const int*)  d_in[2];
    const float* W_c1   = (const float*)d_in[3];
    const float* g0     = (const float*)d_in[4];
    const float* b0     = (const float*)d_in[5];
    const float* W_c12  = (const float*)d_in[6];
    const float* g02    = (const float*)d_in[7];
    const float* b02    = (const float*)d_in[8];
    const float* W_c2   = (const float*)d_in[9];
    const float* W_c3   = (const float*)d_in[10];
    const float* g2     = (const float*)d_in[11];
    const float* b2     = (const float*)d_in[12];
    const float* W_r1   = (const float*)d_in[13];
    const float* rg0    = (const float*)d_in[14];
    const float* rb0    = (const float*)d_in[15];
    const float* W_r12  = (const float*)d_in[16];
    const float* rg02   = (const float*)d_in[17];
    const float* rb02   = (const float*)d_in[18];
    const float* W_r2   = (const float*)d_in[19];
    const float* rg1    = (const float*)d_in[20];
    const float* rb1    = (const float*)d_in[21];
    const float* W_r3   = (const float*)d_in[22];
    const float* rg2    = (const float*)d_in[23];
    const float* rb2    = (const float*)d_in[24];
    float* out = (float*)d_out;

    const int n = in_sizes[0] / 16;   // 120000

    float *BA, *BB, *BC, *BD, *SUM, *SQ, *SC, *SH;
    cudaGetSymbolAddress((void**)&BA,  g_bufA);
    cudaGetSymbolAddress((void**)&BB,  g_bufB);
    cudaGetSymbolAddress((void**)&BC,  g_bufC);
    cudaGetSymbolAddress((void**)&BD,  g_bufD);
    cudaGetSymbolAddress((void**)&SUM, g_sum);
    cudaGetSymbolAddress((void**)&SQ,  g_sq);
    cudaGetSymbolAddress((void**)&SC,  g_sc);
    cudaGetSymbolAddress((void**)&SH,  g_sh);

    // allow >48KB dynamic smem where needed
    cudaFuncSetAttribute((const void*)conv_kernel<32, 64, false>,
                         cudaFuncAttributeMaxDynamicSharedMemorySize, (int)smem_for(32, 64));
    cudaFuncSetAttribute((const void*)conv_kernel<64, 64, true>,
                         cudaFuncAttributeMaxDynamicSharedMemorySize, (int)smem_for(64, 64));

    const int TB = 256;
    const int G  = (n + TB - 1) / TB;

    zero_stats_kernel<<<2, 256>>>(SUM, SQ);

    // ===== ResContextBlock (16 -> 32) =====
    // s = bn0(lrelu(conv133(x, W_c1)))
    conv_kernel<16, 32, false><<<G, TB, smem_for(16, 32)>>>(x, nbr133, W_c1, nullptr, nullptr, BA, n);
    stats_kernel<32><<<120, 512>>>(BA, n, SUM + 0, SQ + 0);
    bnfin_kernel<<<1, 64>>>(SUM + 0, SQ + 0, g0, b0, SC + 0, SH + 0, n, 32);
    // s = bn1(lrelu(conv313(bn0_affine(s'), W_c12)))
    conv_kernel<32, 32, true><<<G, TB, smem_for(32, 32)>>>(BA, nbr313, W_c12, SC + 0, SH + 0, BB, n);
    stats_kernel<32><<<120, 512>>>(BB, n, SUM + 64, SQ + 64);
    bnfin_kernel<<<1, 64>>>(SUM + 64, SQ + 64, g02, b02, SC + 64, SH + 64, n, 32);
    // r = lrelu(conv313(x, W_c2))   (bn discarded in source)
    conv_kernel<16, 32, false><<<G, TB, smem_for(16, 32)>>>(x, nbr313, W_c2, nullptr, nullptr, BC, n);
    // r = bn2(lrelu(conv133(r, W_c3)))
    conv_kernel<32, 32, false><<<G, TB, smem_for(32, 32)>>>(BC, nbr133, W_c3, nullptr, nullptr, BA, n);
    stats_kernel<32><<<120, 512>>>(BA, n, SUM + 128, SQ + 128);
    bnfin_kernel<<<1, 64>>>(SUM + 128, SQ + 128, g2, b2, SC + 128, SH + 128, n, 32);
    // y = aff2(r) + aff1(s)  -> BC
    combine_kernel<32><<<(n * 32 + 255) / 256, 256>>>(BA, SC + 128, SH + 128,
                                                      BB, SC + 64,  SH + 64, BC, n * 32);

    // ===== ResBlock (32 -> 64) =====
    // s2 = bn3(lrelu(conv313(y, W_r1)))
    conv_kernel<32, 64, false><<<G, TB, smem_for(32, 64)>>>(BC, nbr313, W_r1, nullptr, nullptr, BA, n);
    stats_kernel<64><<<120, 512>>>(BA, n, SUM + 192, SQ + 192);
    bnfin_kernel<<<1, 64>>>(SUM + 192, SQ + 192, rg0, rb0, SC + 192, SH + 192, n, 64);
    // s2 = bn4(lrelu(conv133(aff3(s2'), W_r12)))
    conv_kernel<64, 64, true><<<G, TB, smem_for(64, 64)>>>(BA, nbr133, W_r12, SC + 192, SH + 192, BB, n);
    stats_kernel<64><<<120, 512>>>(BB, n, SUM + 256, SQ + 256);
    bnfin_kernel<<<1, 64>>>(SUM + 256, SQ + 256, rg02, rb02, SC + 256, SH + 256, n, 64);
    // r2 = bn5(lrelu(conv133(y, W_r2)))
    conv_kernel<32, 64, false><<<G, TB, smem_for(32, 64)>>>(BC, nbr133, W_r2, nullptr, nullptr, BD, n);
    stats_kernel<64><<<120, 512>>>(BD, n, SUM + 320, SQ + 320);
    bnfin_kernel<<<1, 64>>>(SUM + 320, SQ + 320, rg1, rb1, SC + 320, SH + 320, n, 64);
    // r2 = bn6(lrelu(conv313(aff5(r2'), W_r3)))
    conv_kernel<64, 64, true><<<G, TB, smem_for(64, 64)>>>(BD, nbr313, W_r3, SC + 320, SH + 320, BA, n);
    stats_kernel<64><<<120, 512>>>(BA, n, SUM + 384, SQ + 384);
    bnfin_kernel<<<1, 64>>>(SUM + 384, SQ + 384, rg2, rb2, SC + 384, SH + 384, n, 64);
    // out = aff6(r2) + aff4(s2)
    combine_kernel<64><<<(n * 64 + 255) / 256, 256>>>(BA, SC + 384, SH + 384,
                                                      BB, SC + 256, SH + 256, out, n * 64);
}

// round 5
// speedup vs baseline: 1.4421x; 1.4421x over previous
#include <cuda_runtime.h>
#include <math.h>

#define NVOX 120000
#define EPSV 1e-5f

// ---------------- scratch (no dynamic alloc allowed) ----------------
__device__ __align__(16) float g_bufA[NVOX * 64];
__device__ __align__(16) float g_bufB[NVOX * 64];
__device__ __align__(16) float g_bufC[NVOX * 64];
__device__ __align__(16) float g_bufD[NVOX * 64];
__device__ float g_sum[7 * 64];
__device__ float g_sq [7 * 64];
__device__ float g_sc [7 * 64];
__device__ float g_sh [7 * 64];

// ---------------- packed f32x2 helpers ----------------
__device__ __forceinline__ unsigned long long pack2same(float v) {
    unsigned long long r;
    asm("mov.b64 %0, {%1, %1};" : "=l"(r) : "f"(v));
    return r;
}
__device__ __forceinline__ void unpack2(float& lo, float& hi, unsigned long long a) {
    asm("mov.b64 {%0, %1}, %2;" : "=f"(lo), "=f"(hi) : "l"(a));
}
__device__ __forceinline__ void ffma2(unsigned long long& d, unsigned long long a, unsigned long long b) {
    asm("fma.rn.f32x2 %0, %1, %2, %0;" : "+l"(d) : "l"(a), "l"(b));
}

template <int CT>
__device__ __forceinline__ void mac_row(unsigned long long* acc, float v, const float* w) {
    unsigned long long vv = pack2same(v);
    const ulonglong2* w2 = reinterpret_cast<const ulonglong2*>(w);
#pragma unroll
    for (int q = 0; q < CT / 4; q++) {
        ulonglong2 ww = w2[q];
        ffma2(acc[2 * q + 0], vv, ww.x);
        ffma2(acc[2 * q + 1], vv, ww.y);
    }
}

// ---------------- submanifold conv: out = lrelu( sum_k gather_k(in)@W_k ) ----------------
// COUT tiled by CT via blockIdx.y. Warp-ballot neighbor skip; predicated gather
// loads (zero for invalid lanes). Optional per-input-channel affine (previous
// stage's BN) applied to VALID gathered rows only — matches zero-pad-row ref.
template <int CIN, int COUT, int CT, bool AFFINE>
__global__ void __launch_bounds__(256)
conv_kernel(const float* __restrict__ in, const int* __restrict__ nbr,
            const float* __restrict__ W,
            const float* __restrict__ sc, const float* __restrict__ sh,
            float* __restrict__ out, int n) {
    extern __shared__ __align__(16) float smem[];
    float* ws  = smem;                  // 9*CIN*CT
    float* csc = ws + 9 * CIN * CT;     // CIN
    float* csh = csc + CIN;             // CIN
    const int tid = threadIdx.x;
    const int tb  = blockIdx.y * CT;

    for (int i = tid; i < 9 * CIN * CT; i += blockDim.x) {
        int kci = i / CT;
        int co  = i - kci * CT;
        ws[i] = W[kci * COUT + tb + co];
    }
    if (AFFINE) {
        for (int i = tid; i < CIN; i += blockDim.x) { csc[i] = sc[i]; csh[i] = sh[i]; }
    }
    __syncthreads();

    const int row = blockIdx.x * blockDim.x + tid;
    if ((row & ~31) >= n) return;       // whole-warp out of range
    const bool rok = row < n;

    // preload all 9 indices (invalid lanes -> sentinel n)
    const int* nb = nbr + (size_t)row * 9;
    int idx[9];
#pragma unroll
    for (int k = 0; k < 9; k++) idx[k] = rok ? __ldg(nb + k) : n;

    unsigned long long acc[CT / 2];
#pragma unroll
    for (int i = 0; i < CT / 2; i++) acc[i] = 0ull;

#pragma unroll
    for (int k = 0; k < 9; k++) {
        const int j = idx[k];
        const bool v = j < n;
        if (!__any_sync(0xffffffffu, v)) continue;   // whole warp skips this offset
        const float4* xr = reinterpret_cast<const float4*>(in + (size_t)j * CIN);
        const float* wk = ws + k * CIN * CT;
#pragma unroll
        for (int c4 = 0; c4 < CIN / 4; c4++) {
            float4 val = make_float4(0.f, 0.f, 0.f, 0.f);
            if (v) {
                val = xr[c4];
                if (AFFINE) {
                    val.x = fmaf(val.x, csc[4 * c4 + 0], csh[4 * c4 + 0]);
                    val.y = fmaf(val.y, csc[4 * c4 + 1], csh[4 * c4 + 1]);
                    val.z = fmaf(val.z, csc[4 * c4 + 2], csh[4 * c4 + 2]);
                    val.w = fmaf(val.w, csc[4 * c4 + 3], csh[4 * c4 + 3]);
                }
            }
            const float* w0 = wk + (4 * c4) * CT;
            mac_row<CT>(acc, val.x, w0);
            mac_row<CT>(acc, val.y, w0 + CT);
            mac_row<CT>(acc, val.z, w0 + 2 * CT);
            mac_row<CT>(acc, val.w, w0 + 3 * CT);
        }
    }

    if (rok) {
        float* o = out + (size_t)row * COUT + tb;
#pragma unroll
        for (int i = 0; i < CT / 2; i++) {
            float lo, hi;
            unpack2(lo, hi, acc[i]);
            lo = lo > 0.f ? lo : 0.01f * lo;   // leaky relu, slope 0.01
            hi = hi > 0.f ? hi : 0.01f * hi;
            reinterpret_cast<float2*>(o)[i] = make_float2(lo, hi);
        }
    }
}

// ---------------- per-channel sum / sumsq over [n, C] ----------------
template <int C>
__global__ void stats_kernel(const float* __restrict__ d, int n,
                             float* __restrict__ sum, float* __restrict__ sq) {
    __shared__ float ss[512];
    __shared__ float qq[512];
    const int tid = threadIdx.x;
    const int col = tid % C;
    const int rl  = tid / C;
    const int rpb = blockDim.x / C;
    float s = 0.f, q = 0.f;
    for (int r = blockIdx.x * rpb + rl; r < n; r += gridDim.x * rpb) {
        float v = d[(size_t)r * C + col];
        s += v; q += v * v;
    }
    ss[tid] = s; qq[tid] = q;
    __syncthreads();
    for (int off = blockDim.x / 2; off >= C; off >>= 1) {
        if (tid < off) { ss[tid] += ss[tid + off]; qq[tid] += qq[tid + off]; }
        __syncthreads();
    }
    if (tid < C) {
        atomicAdd(sum + tid, ss[tid]);
        atomicAdd(sq + tid, qq[tid]);
    }
}

// ---------------- BN finalize: scale = g/sqrt(var+eps), shift = b - mean*scale ----------------
__global__ void bnfin_kernel(const float* __restrict__ sum, const float* __restrict__ sq,
                             const float* __restrict__ g, const float* __restrict__ b,
                             float* __restrict__ scale, float* __restrict__ shift,
                             int n, int C) {
    int i = threadIdx.x;
    if (i >= C) return;
    float inv_n = 1.0f / (float)n;
    float m   = sum[i] * inv_n;
    float var = sq[i] * inv_n - m * m;   // biased variance (jnp.var default)
    float s   = g[i] / sqrtf(var + EPSV);
    scale[i] = s;
    shift[i] = b[i] - m * s;
}

// ---------------- out = aff(a) + aff(b) elementwise ----------------
template <int C>
__global__ void combine_kernel(const float* __restrict__ a, const float* __restrict__ sa, const float* __restrict__ ha,
                               const float* __restrict__ b, const float* __restrict__ sb, const float* __restrict__ hb,
                               float* __restrict__ o, int total) {
    int i = blockIdx.x * blockDim.x + threadIdx.x;
    if (i >= total) return;
    int c = i & (C - 1);
    o[i] = fmaf(a[i], sa[c], ha[c]) + fmaf(b[i], sb[c], hb[c]);
}

__global__ void zero_stats_kernel(float* __restrict__ sum, float* __restrict__ sq) {
    int i = blockIdx.x * blockDim.x + threadIdx.x;
    if (i < 7 * 64) { sum[i] = 0.f; sq[i] = 0.f; }
}

// ---------------- host launch sequence ----------------
static constexpr size_t smem_for(int cin, int ct) {
    return (size_t)(9 * cin * ct + 2 * cin) * sizeof(float);
}

extern "C" void kernel_launch(void* const* d_in, const int* in_sizes, int n_in,
                              void* d_out, int out_size) {
    const float* x      = (const float*)d_in[0];
    const int*   nbr133 = (const int*)  d_in[1];
    const int*   nbr313 = (const int*)  d_in[2];
    const float* W_c1   = (const float*)d_in[3];
    const float* g0     = (const float*)d_in[4];
    const float* b0     = (const float*)d_in[5];
    const float* W_c12  = (const float*)d_in[6];
    const float* g02    = (const float*)d_in[7];
    const float* b02    = (const float*)d_in[8];
    const float* W_c2   = (const float*)d_in[9];
    const float* W_c3   = (const float*)d_in[10];
    const float* g2     = (const float*)d_in[11];
    const float* b2     = (const float*)d_in[12];
    const float* W_r1   = (const float*)d_in[13];
    const float* rg0    = (const float*)d_in[14];
    const float* rb0    = (const float*)d_in[15];
    const float* W_r12  = (const float*)d_in[16];
    const float* rg02   = (const float*)d_in[17];
    const float* rb02   = (const float*)d_in[18];
    const float* W_r2   = (const float*)d_in[19];
    const float* rg1    = (const float*)d_in[20];
    const float* rb1    = (const float*)d_in[21];
    const float* W_r3   = (const float*)d_in[22];
    const float* rg2    = (const float*)d_in[23];
    const float* rb2    = (const float*)d_in[24];
    float* out = (float*)d_out;

    const int n = in_sizes[0] / 16;   // 120000

    float *BA, *BB, *BC, *BD, *SUM, *SQ, *SC, *SH;
    cudaGetSymbolAddress((void**)&BA,  g_bufA);
    cudaGetSymbolAddress((void**)&BB,  g_bufB);
    cudaGetSymbolAddress((void**)&BC,  g_bufC);
    cudaGetSymbolAddress((void**)&BD,  g_bufD);
    cudaGetSymbolAddress((void**)&SUM, g_sum);
    cudaGetSymbolAddress((void**)&SQ,  g_sq);
    cudaGetSymbolAddress((void**)&SC,  g_sc);
    cudaGetSymbolAddress((void**)&SH,  g_sh);

    // >48KB dynamic smem only for the 64-cin kernels (73.9KB -> 3 CTAs/SM)
    cudaFuncSetAttribute((const void*)conv_kernel<64, 64, 32, true>,
                         cudaFuncAttributeMaxDynamicSharedMemorySize, (int)smem_for(64, 32));

    const int TB = 256;
    const int G  = (n + TB - 1) / TB;

    zero_stats_kernel<<<2, 256>>>(SUM, SQ);

    // ===== ResContextBlock (16 -> 32) =====
    conv_kernel<16, 32, 32, false><<<dim3(G, 1), TB, smem_for(16, 32)>>>(x, nbr133, W_c1, nullptr, nullptr, BA, n);
    stats_kernel<32><<<148, 512>>>(BA, n, SUM + 0, SQ + 0);
    bnfin_kernel<<<1, 64>>>(SUM + 0, SQ + 0, g0, b0, SC + 0, SH + 0, n, 32);

    conv_kernel<32, 32, 32, true><<<dim3(G, 1), TB, smem_for(32, 32)>>>(BA, nbr313, W_c12, SC + 0, SH + 0, BB, n);
    stats_kernel<32><<<148, 512>>>(BB, n, SUM + 64, SQ + 64);
    bnfin_kernel<<<1, 64>>>(SUM + 64, SQ + 64, g02, b02, SC + 64, SH + 64, n, 32);

    conv_kernel<16, 32, 32, false><<<dim3(G, 1), TB, smem_for(16, 32)>>>(x, nbr313, W_c2, nullptr, nullptr, BC, n);
    conv_kernel<32, 32, 32, false><<<dim3(G, 1), TB, smem_for(32, 32)>>>(BC, nbr133, W_c3, nullptr, nullptr, BA, n);
    stats_kernel<32><<<148, 512>>>(BA, n, SUM + 128, SQ + 128);
    bnfin_kernel<<<1, 64>>>(SUM + 128, SQ + 128, g2, b2, SC + 128, SH + 128, n, 32);

    combine_kernel<32><<<(n * 32 + 255) / 256, 256>>>(BA, SC + 128, SH + 128,
                                                      BB, SC + 64,  SH + 64, BC, n * 32);

    // ===== ResBlock (32 -> 64) =====
    conv_kernel<32, 64, 32, false><<<dim3(G, 2), TB, smem_for(32, 32)>>>(BC, nbr313, W_r1, nullptr, nullptr, BA, n);
    stats_kernel<64><<<148, 512>>>(BA, n, SUM + 192, SQ + 192);
    bnfin_kernel<<<1, 64>>>(SUM + 192, SQ + 192, rg0, rb0, SC + 192, SH + 192, n, 64);

    conv_kernel<64, 64, 32, true><<<dim3(G, 2), TB, smem_for(64, 32)>>>(BA, nbr133, W_r12, SC + 192, SH + 192, BB, n);
    stats_kernel<64><<<148, 512>>>(BB, n, SUM + 256, SQ + 256);
    bnfin_kernel<<<1, 64>>>(SUM + 256, SQ + 256, rg02, rb02, SC + 256, SH + 256, n, 64);

    conv_kernel<32, 64, 32, false><<<dim3(G, 2), TB, smem_for(32, 32)>>>(BC, nbr133, W_r2, nullptr, nullptr, BD, n);
    stats_kernel<64><<<148, 512>>>(BD, n, SUM + 320, SQ + 320);
    bnfin_kernel<<<1, 64>>>(SUM + 320, SQ + 320, rg1, rb1, SC + 320, SH + 320, n, 64);

    conv_kernel<64, 64, 32, true><<<dim3(G, 2), TB, smem_for(64, 32)>>>(BD, nbr313, W_r3, SC + 320, SH + 320, BA, n);
    stats_kernel<64><<<148, 512>>>(BA, n, SUM + 384, SQ + 384);
    bnfin_kernel<<<1, 64>>>(SUM + 384, SQ + 384, rg2, rb2, SC + 384, SH + 384, n, 64);

    combine_kernel<64><<<(n * 64 + 255) / 256, 256>>>(BA, SC + 384, SH + 384,
                                                      BB, SC + 256, SH + 256, out, n * 64);
}

// round 8
// speedup vs baseline: 3.5369x; 2.4526x over previous
#include <cuda_runtime.h>
#include <math.h>

#define NVOX 120000
#define EPSV 1e-5f

// ---------------- scratch (no dynamic alloc allowed) ----------------
__device__ __align__(16) float g_bufA[NVOX * 64];
__device__ __align__(16) float g_bufB[NVOX * 64];
__device__ __align__(16) float g_bufC[NVOX * 64];
__device__ __align__(16) float g_bufD[NVOX * 64];
__device__ float g_sum[7 * 64];
__device__ float g_sq [7 * 64];
__device__ float g_sc [7 * 64];
__device__ float g_sh [7 * 64];
// sort scratch (one per rulebook)
__device__ int g_permA[NVOX];
__device__ int g_permB[NVOX];
__device__ int g_maskA[NVOX];
__device__ int g_maskB[NVOX];
__device__ int g_histA[512];
__device__ int g_histB[512];

// ---------------- packed f32x2 helpers ----------------
__device__ __forceinline__ unsigned long long pack2same(float v) {
    unsigned long long r;
    asm("mov.b64 %0, {%1, %1};" : "=l"(r) : "f"(v));
    return r;
}
__device__ __forceinline__ void unpack2(float& lo, float& hi, unsigned long long a) {
    asm("mov.b64 {%0, %1}, %2;" : "=f"(lo), "=f"(hi) : "l"(a));
}
__device__ __forceinline__ void ffma2(unsigned long long& d, unsigned long long a, unsigned long long b) {
    asm("fma.rn.f32x2 %0, %1, %2, %0;" : "+l"(d) : "l"(a), "l"(b));
}

template <int CT>
__device__ __forceinline__ void mac_row(unsigned long long* acc, float v, const float* w) {
    unsigned long long vv = pack2same(v);
    const ulonglong2* w2 = reinterpret_cast<const ulonglong2*>(w);
#pragma unroll
    for (int q = 0; q < CT / 4; q++) {
        ulonglong2 ww = w2[q];
        ffma2(acc[2 * q + 0], vv, ww.x);
        ffma2(acc[2 * q + 1], vv, ww.y);
    }
}

// ================= mask-bucket counting sort (per rulebook) =================
// rows grouped by their 9-bit validity mask -> warps become mask-uniform, so
// the warp-ballot offset skip in the conv matches per-ROW sparsity (~1.17/9)
// instead of per-warp union (~5/9).
__global__ void mask_hist_kernel(const int* __restrict__ nbr, int n,
                                 int* __restrict__ hist, int* __restrict__ masks) {
    __shared__ int lh[512];
    for (int i = threadIdx.x; i < 512; i += blockDim.x) lh[i] = 0;
    __syncthreads();
    int r = blockIdx.x * blockDim.x + threadIdx.x;
    if (r < n) {
        const int* nb = nbr + (size_t)r * 9;
        int m = 0;
#pragma unroll
        for (int k = 0; k < 9; k++) m |= (nb[k] < n) << k;
        masks[r] = m;
        atomicAdd(&lh[m], 1);
    }
    __syncthreads();
    for (int i = threadIdx.x; i < 512; i += blockDim.x)
        if (lh[i]) atomicAdd(&hist[i], lh[i]);
}

__global__ void scan_kernel(int* __restrict__ hist) {  // 1 block, 512 threads, exclusive
    __shared__ int tmp[512];
    int t = threadIdx.x;
    tmp[t] = hist[t];
    __syncthreads();
    for (int off = 1; off < 512; off <<= 1) {
        int add = (t >= off) ? tmp[t - off] : 0;
        __syncthreads();
        tmp[t] += add;
        __syncthreads();
    }
    hist[t] = (t == 0) ? 0 : tmp[t - 1];
}

__global__ void scatter_kernel(const int* __restrict__ masks, int n,
                               int* __restrict__ offs, int* __restrict__ perm) {
    int r = blockIdx.x * blockDim.x + threadIdx.x;
    int lane = threadIdx.x & 31;
    int m = (r < n) ? masks[r] : -1;
    unsigned grp = __match_any_sync(0xffffffffu, m);
    int leader = __ffs(grp) - 1;
    int rank = __popc(grp & ((1u << lane) - 1u));
    int base = 0;
    if (lane == leader && m >= 0) base = atomicAdd(&offs[m], __popc(grp));
    base = __shfl_sync(0xffffffffu, base, leader);
    if (m >= 0) perm[base + rank] = r;
}

// ---------------- submanifold conv: out = lrelu( sum_k gather_k(in)@W_k ) ----------------
// Rows visited through perm (mask-sorted). COUT tiled by CT via blockIdx.y.
// Optional per-input-channel affine (previous BN) on VALID gathered rows only.
template <int CIN, int COUT, int CT, bool AFFINE>
__global__ void __launch_bounds__(256)
conv_kernel(const float* __restrict__ in, const int* __restrict__ nbr,
            const int* __restrict__ perm,
            const float* __restrict__ W,
            const float* __restrict__ sc, const float* __restrict__ sh,
            float* __restrict__ out, int n) {
    extern __shared__ __align__(16) float smem[];
    float* ws  = smem;                  // 9*CIN*CT
    float* csc = ws + 9 * CIN * CT;     // CIN
    float* csh = csc + CIN;             // CIN
    const int tid = threadIdx.x;
    const int tb  = blockIdx.y * CT;

    for (int i = tid; i < 9 * CIN * CT; i += blockDim.x) {
        int kci = i / CT;
        int co  = i - kci * CT;
        ws[i] = W[kci * COUT + tb + co];
    }
    if (AFFINE) {
        for (int i = tid; i < CIN; i += blockDim.x) { csc[i] = sc[i]; csh[i] = sh[i]; }
    }
    __syncthreads();

    const int gid = blockIdx.x * blockDim.x + tid;
    const bool rok = gid < n;
    const int row = rok ? perm[gid] : 0;

    // preload all 9 indices (invalid lanes -> sentinel n); keep all lanes alive
    const int* nb = nbr + (size_t)row * 9;
    int idx[9];
#pragma unroll
    for (int k = 0; k < 9; k++) idx[k] = rok ? __ldg(nb + k) : n;

    unsigned long long acc[CT / 2];
#pragma unroll
    for (int i = 0; i < CT / 2; i++) acc[i] = 0ull;

#pragma unroll
    for (int k = 0; k < 9; k++) {
        const int j = idx[k];
        const bool v = j < n;
        if (!__any_sync(0xffffffffu, v)) continue;   // exact skip (mask-uniform warps)
        const float4* xr = reinterpret_cast<const float4*>(in + (size_t)j * CIN);
        const float* wk = ws + k * CIN * CT;
#pragma unroll
        for (int c4 = 0; c4 < CIN / 4; c4++) {
            float4 val = make_float4(0.f, 0.f, 0.f, 0.f);
            if (v) {
                val = xr[c4];
                if (AFFINE) {
                    val.x = fmaf(val.x, csc[4 * c4 + 0], csh[4 * c4 + 0]);
                    val.y = fmaf(val.y, csc[4 * c4 + 1], csh[4 * c4 + 1]);
                    val.z = fmaf(val.z, csc[4 * c4 + 2], csh[4 * c4 + 2]);
                    val.w = fmaf(val.w, csc[4 * c4 + 3], csh[4 * c4 + 3]);
                }
            }
            const float* w0 = wk + (4 * c4) * CT;
            mac_row<CT>(acc, val.x, w0);
            mac_row<CT>(acc, val.y, w0 + CT);
            mac_row<CT>(acc, val.z, w0 + 2 * CT);
            mac_row<CT>(acc, val.w, w0 + 3 * CT);
        }
    }

    if (rok) {
        float* o = out + (size_t)row * COUT + tb;
#pragma unroll
        for (int i = 0; i < CT / 2; i++) {
            float lo, hi;
            unpack2(lo, hi, acc[i]);
            lo = lo > 0.f ? lo : 0.01f * lo;   // leaky relu, slope 0.01
            hi = hi > 0.f ? hi : 0.01f * hi;
            reinterpret_cast<float2*>(o)[i] = make_float2(lo, hi);
        }
    }
}

// ---------------- per-channel sum / sumsq over [n, C] ----------------
template <int C>
__global__ void stats_kernel(const float* __restrict__ d, int n,
                             float* __restrict__ sum, float* __restrict__ sq) {
    __shared__ float ss[512];
    __shared__ float qq[512];
    const int tid = threadIdx.x;
    const int col = tid % C;
    const int rl  = tid / C;
    const int rpb = blockDim.x / C;
    float s = 0.f, q = 0.f;
    for (int r = blockIdx.x * rpb + rl; r < n; r += gridDim.x * rpb) {
        float v = d[(size_t)r * C + col];
        s += v; q += v * v;
    }
    ss[tid] = s; qq[tid] = q;
    __syncthreads();
    for (int off = blockDim.x / 2; off >= C; off >>= 1) {
        if (tid < off) { ss[tid] += ss[tid + off]; qq[tid] += qq[tid + off]; }
        __syncthreads();
    }
    if (tid < C) {
        atomicAdd(sum + tid, ss[tid]);
        atomicAdd(sq + tid, qq[tid]);
    }
}

// ---------------- BN finalize ----------------
__global__ void bnfin_kernel(const float* __restrict__ sum, const float* __restrict__ sq,
                             const float* __restrict__ g, const float* __restrict__ b,
                             float* __restrict__ scale, float* __restrict__ shift,
                             int n, int C) {
    int i = threadIdx.x;
    if (i >= C) return;
    float inv_n = 1.0f / (float)n;
    float m   = sum[i] * inv_n;
    float var = sq[i] * inv_n - m * m;   // biased variance
    float s   = g[i] / sqrtf(var + EPSV);
    scale[i] = s;
    shift[i] = b[i] - m * s;
}

// ---------------- out = aff(a) + aff(b) elementwise ----------------
template <int C>
__global__ void combine_kernel(const float* __restrict__ a, const float* __restrict__ sa, const float* __restrict__ ha,
                               const float* __restrict__ b, const float* __restrict__ sb, const float* __restrict__ hb,
                               float* __restrict__ o, int total) {
    int i = blockIdx.x * blockDim.x + threadIdx.x;
    if (i >= total) return;
    int c = i & (C - 1);
    o[i] = fmaf(a[i], sa[c], ha[c]) + fmaf(b[i], sb[c], hb[c]);
}

__global__ void zero_kernel(float* __restrict__ sum, float* __restrict__ sq,
                            int* __restrict__ hA, int* __restrict__ hB) {
    int i = blockIdx.x * blockDim.x + threadIdx.x;
    if (i < 7 * 64) { sum[i] = 0.f; sq[i] = 0.f; }
    if (i < 512) { hA[i] = 0; hB[i] = 0; }
}

// ---------------- host launch sequence ----------------
static constexpr size_t smem_for(int cin, int ct) {
    return (size_t)(9 * cin * ct + 2 * cin) * sizeof(float);
}

extern "C" void kernel_launch(void* const* d_in, const int* in_sizes, int n_in,
                              void* d_out, int out_size) {
    const float* x      = (const float*)d_in[0];
    const int*   nbr133 = (const int*)  d_in[1];
    const int*   nbr313 = (const int*)  d_in[2];
    const float* W_c1   = (const float*)d_in[3];
    const float* g0     = (const float*)d_in[4];
    const float* b0     = (const float*)d_in[5];
    const float* W_c12  = (const float*)d_in[6];
    const float* g02    = (const float*)d_in[7];
    const float* b02    = (const float*)d_in[8];
    const float* W_c2   = (const float*)d_in[9];
    const float* W_c3   = (const float*)d_in[10];
    const float* g2     = (const float*)d_in[11];
    const float* b2     = (const float*)d_in[12];
    const float* W_r1   = (const float*)d_in[13];
    const float* rg0    = (const float*)d_in[14];
    const float* rb0    = (const float*)d_in[15];
    const float* W_r12  = (const float*)d_in[16];
    const float* rg02   = (const float*)d_in[17];
    const float* rb02   = (const float*)d_in[18];
    const float* W_r2   = (const float*)d_in[19];
    const float* rg1    = (const float*)d_in[20];
    const float* rb1    = (const float*)d_in[21];
    const float* W_r3   = (const float*)d_in[22];
    const float* rg2    = (const float*)d_in[23];
    const float* rb2    = (const float*)d_in[24];
    float* out = (float*)d_out;

    const int n = in_sizes[0] / 16;   // 120000

    float *BA, *BB, *BC, *BD, *SUM, *SQ, *SC, *SH;
    int *PA, *PB, *MA, *MB, *HA, *HB;
    cudaGetSymbolAddress((void**)&BA,  g_bufA);
    cudaGetSymbolAddress((void**)&BB,  g_bufB);
    cudaGetSymbolAddress((void**)&BC,  g_bufC);
    cudaGetSymbolAddress((void**)&BD,  g_bufD);
    cudaGetSymbolAddress((void**)&SUM, g_sum);
    cudaGetSymbolAddress((void**)&SQ,  g_sq);
    cudaGetSymbolAddress((void**)&SC,  g_sc);
    cudaGetSymbolAddress((void**)&SH,  g_sh);
    cudaGetSymbolAddress((void**)&PA,  g_permA);
    cudaGetSymbolAddress((void**)&PB,  g_permB);
    cudaGetSymbolAddress((void**)&MA,  g_maskA);
    cudaGetSymbolAddress((void**)&MB,  g_maskB);
    cudaGetSymbolAddress((void**)&HA,  g_histA);
    cudaGetSymbolAddress((void**)&HB,  g_histB);

    cudaFuncSetAttribute((const void*)conv_kernel<64, 64, 32, true>,
                         cudaFuncAttributeMaxDynamicSharedMemorySize, (int)smem_for(64, 32));

    const int TB = 256;
    const int G  = (n + TB - 1) / TB;

    // ----- prologue: zero + mask-bucket sort of both rulebooks -----
    zero_kernel<<<2, 512>>>(SUM, SQ, HA, HB);
    mask_hist_kernel<<<G, TB>>>(nbr133, n, HA, MA);
    mask_hist_kernel<<<G, TB>>>(nbr313, n, HB, MB);
    scan_kernel<<<1, 512>>>(HA);
    scan_kernel<<<1, 512>>>(HB);
    scatter_kernel<<<G, TB>>>(MA, n, HA, PA);
    scatter_kernel<<<G, TB>>>(MB, n, HB, PB);

    // ===== ResContextBlock (16 -> 32) =====
    conv_kernel<16, 32, 32, false><<<dim3(G, 1), TB, smem_for(16, 32)>>>(x, nbr133, PA, W_c1, nullptr, nullptr, BA, n);
    stats_kernel<32><<<148, 512>>>(BA, n, SUM + 0, SQ + 0);
    bnfin_kernel<<<1, 64>>>(SUM + 0, SQ + 0, g0, b0, SC + 0, SH + 0, n, 32);

    conv_kernel<32, 32, 32, true><<<dim3(G, 1), TB, smem_for(32, 32)>>>(BA, nbr313, PB, W_c12, SC + 0, SH + 0, BB, n);
    stats_kernel<32><<<148, 512>>>(BB, n, SUM + 64, SQ + 64);
    bnfin_kernel<<<1, 64>>>(SUM + 64, SQ + 64, g02, b02, SC + 64, SH + 64, n, 32);

    conv_kernel<16, 32, 32, false><<<dim3(G, 1), TB, smem_for(16, 32)>>>(x, nbr313, PB, W_c2, nullptr, nullptr, BC, n);
    conv_kernel<32, 32, 32, false><<<dim3(G, 1), TB, smem_for(32, 32)>>>(BC, nbr133, PA, W_c3, nullptr, nullptr, BA, n);
    stats_kernel<32><<<148, 512>>>(BA, n, SUM + 128, SQ + 128);
    bnfin_kernel<<<1, 64>>>(SUM + 128, SQ + 128, g2, b2, SC + 128, SH + 128, n, 32);

    combine_kernel<32><<<(n * 32 + 255) / 256, 256>>>(BA, SC + 128, SH + 128,
                                                      BB, SC + 64,  SH + 64, BC, n * 32);

    // ===== ResBlock (32 -> 64) =====
    conv_kernel<32, 64, 32, false><<<dim3(G, 2), TB, smem_for(32, 32)>>>(BC, nbr313, PB, W_r1, nullptr, nullptr, BA, n);
    stats_kernel<64><<<148, 512>>>(BA, n, SUM + 192, SQ + 192);
    bnfin_kernel<<<1, 64>>>(SUM + 192, SQ + 192, rg0, rb0, SC + 192, SH + 192, n, 64);

    conv_kernel<64, 64, 32, true><<<dim3(G, 2), TB, smem_for(64, 32)>>>(BA, nbr133, PA, W_r12, SC + 192, SH + 192, BB, n);
    stats_kernel<64><<<148, 512>>>(BB, n, SUM + 256, SQ + 256);
    bnfin_kernel<<<1, 64>>>(SUM + 256, SQ + 256, rg02, rb02, SC + 256, SH + 256, n, 64);

    conv_kernel<32, 64, 32, false><<<dim3(G, 2), TB, smem_for(32, 32)>>>(BC, nbr133, PA, W_r2, nullptr, nullptr, BD, n);
    stats_kernel<64><<<148, 512>>>(BD, n, SUM + 320, SQ + 320);
    bnfin_kernel<<<1, 64>>>(SUM + 320, SQ + 320, rg1, rb1, SC + 320, SH + 320, n, 64);

    conv_kernel<64, 64, 32, true><<<dim3(G, 2), TB, smem_for(64, 32)>>>(BD, nbr313, PB, W_r3, SC + 320, SH + 320, BA, n);
    stats_kernel<64><<<148, 512>>>(BA, n, SUM + 384, SQ + 384);
    bnfin_kernel<<<1, 64>>>(SUM + 384, SQ + 384, rg2, rb2, SC + 384, SH + 384, n, 64);

    combine_kernel<64><<<(n * 64 + 255) / 256, 256>>>(BA, SC + 384, SH + 384,
                                                      BB, SC + 256, SH + 256, out, n * 64);
}

// round 9
// speedup vs baseline: 3.8095x; 1.0771x over previous
#include <cuda_runtime.h>
#include <math.h>

#define NVOX 120000
#define EPSV 1e-5f

// ---------------- scratch (no dynamic alloc allowed) ----------------
__device__ __align__(16) float g_bufA[NVOX * 64];
__device__ __align__(16) float g_bufB[NVOX * 64];
__device__ __align__(16) float g_bufC[NVOX * 64];
__device__ __align__(16) float g_bufD[NVOX * 64];
__device__ float g_sum[7 * 64];
__device__ float g_sq [7 * 64];
__device__ float g_sc [7 * 64];
__device__ float g_sh [7 * 64];
__device__ int   g_ctr[8];
// sort scratch (one per rulebook)
__device__ int g_permA[NVOX];
__device__ int g_permB[NVOX];
__device__ int g_maskA[NVOX];
__device__ int g_maskB[NVOX];
__device__ int g_histA[512];
__device__ int g_histB[512];

// ---------------- packed f32x2 helpers ----------------
__device__ __forceinline__ unsigned long long pack2same(float v) {
    unsigned long long r;
    asm("mov.b64 %0, {%1, %1};" : "=l"(r) : "f"(v));
    return r;
}
__device__ __forceinline__ void unpack2(float& lo, float& hi, unsigned long long a) {
    asm("mov.b64 {%0, %1}, %2;" : "=f"(lo), "=f"(hi) : "l"(a));
}
__device__ __forceinline__ void ffma2(unsigned long long& d, unsigned long long a, unsigned long long b) {
    asm("fma.rn.f32x2 %0, %1, %2, %0;" : "+l"(d) : "l"(a), "l"(b));
}

template <int CT>
__device__ __forceinline__ void mac_row(unsigned long long* acc, float v, const float* w) {
    unsigned long long vv = pack2same(v);
    const ulonglong2* w2 = reinterpret_cast<const ulonglong2*>(w);
#pragma unroll
    for (int q = 0; q < CT / 4; q++) {
        ulonglong2 ww = w2[q];
        ffma2(acc[2 * q + 0], vv, ww.x);
        ffma2(acc[2 * q + 1], vv, ww.y);
    }
}

// ================= mask-bucket counting sort (both rulebooks, y-dim picks) ==
__global__ void mask_hist_kernel(const int* __restrict__ nbrA, const int* __restrict__ nbrB,
                                 int n, int* __restrict__ histA, int* __restrict__ histB,
                                 int* __restrict__ masksA, int* __restrict__ masksB) {
    const int* nbr   = blockIdx.y ? nbrB : nbrA;
    int* hist        = blockIdx.y ? histB : histA;
    int* masks       = blockIdx.y ? masksB : masksA;
    __shared__ int lh[512];
    for (int i = threadIdx.x; i < 512; i += blockDim.x) lh[i] = 0;
    __syncthreads();
    int r = blockIdx.x * blockDim.x + threadIdx.x;
    if (r < n) {
        const int* nb = nbr + (size_t)r * 9;
        int m = 0;
#pragma unroll
        for (int k = 0; k < 9; k++) m |= (nb[k] < n) << k;
        masks[r] = m;
        atomicAdd(&lh[m], 1);
    }
    __syncthreads();
    for (int i = threadIdx.x; i < 512; i += blockDim.x)
        if (lh[i]) atomicAdd(&hist[i], lh[i]);
}

__global__ void scan_kernel(int* __restrict__ histA, int* __restrict__ histB) {
    int* hist = blockIdx.x ? histB : histA;
    __shared__ int tmp[512];
    int t = threadIdx.x;
    tmp[t] = hist[t];
    __syncthreads();
    for (int off = 1; off < 512; off <<= 1) {
        int add = (t >= off) ? tmp[t - off] : 0;
        __syncthreads();
        tmp[t] += add;
        __syncthreads();
    }
    hist[t] = (t == 0) ? 0 : tmp[t - 1];
}

__global__ void scatter_kernel(const int* __restrict__ masksA, const int* __restrict__ masksB,
                               int n, int* __restrict__ offsA, int* __restrict__ offsB,
                               int* __restrict__ permA, int* __restrict__ permB) {
    const int* masks = blockIdx.y ? masksB : masksA;
    int* offs        = blockIdx.y ? offsB : offsA;
    int* perm        = blockIdx.y ? permB : permA;
    int r = blockIdx.x * blockDim.x + threadIdx.x;
    int lane = threadIdx.x & 31;
    int m = (r < n) ? masks[r] : -1;
    unsigned grp = __match_any_sync(0xffffffffu, m);
    int leader = __ffs(grp) - 1;
    int rank = __popc(grp & ((1u << lane) - 1u));
    int base = 0;
    if (lane == leader && m >= 0) base = atomicAdd(&offs[m], __popc(grp));
    base = __shfl_sync(0xffffffffu, base, leader);
    if (m >= 0) perm[base + rank] = r;
}

// ---------------- submanifold conv (persistent grid-stride over row tiles) --
// out = lrelu( sum_k gather_k(in)@W_k ); rows via mask-sorted perm.
// COUT tiled by CT via blockIdx.y; weights staged once per CTA (float4).
template <int CIN, int COUT, int CT, bool AFFINE>
__global__ void __launch_bounds__(256)
conv_kernel(const float* __restrict__ in, const int* __restrict__ nbr,
            const int* __restrict__ perm,
            const float* __restrict__ W,
            const float* __restrict__ sc, const float* __restrict__ sh,
            float* __restrict__ out, int n, int ntiles) {
    extern __shared__ __align__(16) float smem[];
    float* ws  = smem;                  // 9*CIN*CT
    float* csc = ws + 9 * CIN * CT;     // CIN
    float* csh = csc + CIN;             // CIN
    const int tid = threadIdx.x;
    const int tb  = blockIdx.y * CT;

    // float4 weight staging: row r = (k*CIN+ci), take CT cols starting at tb
    {
        float4* ws4 = reinterpret_cast<float4*>(ws);
        const float4* W4 = reinterpret_cast<const float4*>(W);
        const int tb4 = tb >> 2;
        const int c4w = COUT >> 2;
        constexpr int TOT4 = 9 * CIN * CT / 4;
        constexpr int Q4 = CT / 4;          // 8, power of 2
#pragma unroll 4
        for (int i = tid; i < TOT4; i += 256) {
            int r = i / Q4;
            int q = i - r * Q4;
            ws4[i] = W4[r * c4w + tb4 + q];
        }
    }
    if (AFFINE) {
        for (int i = tid; i < CIN; i += 256) { csc[i] = sc[i]; csh[i] = sh[i]; }
    }
    __syncthreads();

    for (int t = blockIdx.x; t < ntiles; t += gridDim.x) {
        const int gid = t * 256 + tid;
        const bool rok = gid < n;
        const int row = rok ? perm[gid] : 0;

        const int* nb = nbr + (size_t)row * 9;
        int idx[9];
#pragma unroll
        for (int k = 0; k < 9; k++) idx[k] = rok ? __ldg(nb + k) : n;

        unsigned long long acc[CT / 2];
#pragma unroll
        for (int i = 0; i < CT / 2; i++) acc[i] = 0ull;

#pragma unroll
        for (int k = 0; k < 9; k++) {
            const int j = idx[k];
            const bool v = j < n;
            if (!__any_sync(0xffffffffu, v)) continue;   // exact skip (mask-uniform warps)
            const float4* xr = reinterpret_cast<const float4*>(in + (size_t)j * CIN);
            const float* wk = ws + k * CIN * CT;
#pragma unroll
            for (int c4 = 0; c4 < CIN / 4; c4++) {
                float4 val = make_float4(0.f, 0.f, 0.f, 0.f);
                if (v) {
                    val = xr[c4];
                    if (AFFINE) {
                        val.x = fmaf(val.x, csc[4 * c4 + 0], csh[4 * c4 + 0]);
                        val.y = fmaf(val.y, csc[4 * c4 + 1], csh[4 * c4 + 1]);
                        val.z = fmaf(val.z, csc[4 * c4 + 2], csh[4 * c4 + 2]);
                        val.w = fmaf(val.w, csc[4 * c4 + 3], csh[4 * c4 + 3]);
                    }
                }
                const float* w0 = wk + (4 * c4) * CT;
                mac_row<CT>(acc, val.x, w0);
                mac_row<CT>(acc, val.y, w0 + CT);
                mac_row<CT>(acc, val.z, w0 + 2 * CT);
                mac_row<CT>(acc, val.w, w0 + 3 * CT);
            }
        }

        if (rok) {
            float* o = out + (size_t)row * COUT + tb;
#pragma unroll
            for (int i = 0; i < CT / 2; i++) {
                float lo, hi;
                unpack2(lo, hi, acc[i]);
                lo = lo > 0.f ? lo : 0.01f * lo;   // leaky relu 0.01
                hi = hi > 0.f ? hi : 0.01f * hi;
                reinterpret_cast<float2*>(o)[i] = make_float2(lo, hi);
            }
        }
    }
}

// ---------------- per-channel sum/sumsq + last-block BN finalize ------------
template <int C>
__global__ void statsbn_kernel(const float* __restrict__ d, int n,
                               float* __restrict__ sum, float* __restrict__ sq,
                               const float* __restrict__ g, const float* __restrict__ b,
                               float* __restrict__ scale, float* __restrict__ shift,
                               int* __restrict__ ctr) {
    __shared__ float ss[512];
    __shared__ float qq[512];
    __shared__ int last;
    const int tid = threadIdx.x;
    const int col = tid % C;
    const int rl  = tid / C;
    const int rpb = blockDim.x / C;
    float s = 0.f, q = 0.f;
    for (int r = blockIdx.x * rpb + rl; r < n; r += gridDim.x * rpb) {
        float v = d[(size_t)r * C + col];
        s += v; q += v * v;
    }
    ss[tid] = s; qq[tid] = q;
    __syncthreads();
    for (int off = blockDim.x / 2; off >= C; off >>= 1) {
        if (tid < off) { ss[tid] += ss[tid + off]; qq[tid] += qq[tid + off]; }
        __syncthreads();
    }
    if (tid < C) {
        atomicAdd(sum + tid, ss[tid]);
        atomicAdd(sq + tid, qq[tid]);
    }
    __threadfence();
    __syncthreads();
    if (tid == 0) last = (atomicAdd(ctr, 1) == (int)gridDim.x - 1);
    __syncthreads();
    if (last && tid < C) {
        float inv_n = 1.0f / (float)n;
        float m   = __ldcg(sum + tid) * inv_n;
        float var = __ldcg(sq + tid) * inv_n - m * m;   // biased variance
        float sc2 = g[tid] / sqrtf(var + EPSV);
        scale[tid] = sc2;
        shift[tid] = b[tid] - m * sc2;
    }
}

// ---------------- out = aff(a) + aff(b) elementwise ----------------
template <int C>
__global__ void combine_kernel(const float* __restrict__ a, const float* __restrict__ sa, const float* __restrict__ ha,
                               const float* __restrict__ b, const float* __restrict__ sb, const float* __restrict__ hb,
                               float* __restrict__ o, int total) {
    int i = blockIdx.x * blockDim.x + threadIdx.x;
    if (i >= total) return;
    int c = i & (C - 1);
    o[i] = fmaf(a[i], sa[c], ha[c]) + fmaf(b[i], sb[c], hb[c]);
}

__global__ void zero_kernel(float* __restrict__ sum, float* __restrict__ sq,
                            int* __restrict__ hA, int* __restrict__ hB,
                            int* __restrict__ ctr) {
    int i = blockIdx.x * blockDim.x + threadIdx.x;
    if (i < 7 * 64) { sum[i] = 0.f; sq[i] = 0.f; }
    if (i < 512) { hA[i] = 0; hB[i] = 0; }
    if (i < 8) ctr[i] = 0;
}

// ---------------- host launch sequence ----------------
static constexpr size_t smem_for(int cin, int ct) {
    return (size_t)(9 * cin * ct + 2 * cin) * sizeof(float);
}

template <int CIN, int COUT, int CT, bool AFFINE>
static int persistent_grid(int ntiles) {
    static int occ = -1;
    if (occ < 0) {
        cudaFuncSetAttribute((const void*)conv_kernel<CIN, COUT, CT, AFFINE>,
                             cudaFuncAttributeMaxDynamicSharedMemorySize, (int)smem_for(CIN, CT));
        cudaOccupancyMaxActiveBlocksPerMultiprocessor(&occ, conv_kernel<CIN, COUT, CT, AFFINE>,
                                                      256, smem_for(CIN, CT));
        if (occ < 1) occ = 1;
    }
    int gx = occ * 148;
    return gx < ntiles ? gx : ntiles;
}

extern "C" void kernel_launch(void* const* d_in, const int* in_sizes, int n_in,
                              void* d_out, int out_size) {
    const float* x      = (const float*)d_in[0];
    const int*   nbr133 = (const int*)  d_in[1];
    const int*   nbr313 = (const int*)  d_in[2];
    const float* W_c1   = (const float*)d_in[3];
    const float* g0     = (const float*)d_in[4];
    const float* b0     = (const float*)d_in[5];
    const float* W_c12  = (const float*)d_in[6];
    const float* g02    = (const float*)d_in[7];
    const float* b02    = (const float*)d_in[8];
    const float* W_c2   = (const float*)d_in[9];
    const float* W_c3   = (const float*)d_in[10];
    const float* g2     = (const float*)d_in[11];
    const float* b2     = (const float*)d_in[12];
    const float* W_r1   = (const float*)d_in[13];
    const float* rg0    = (const float*)d_in[14];
    const float* rb0    = (const float*)d_in[15];
    const float* W_r12  = (const float*)d_in[16];
    const float* rg02   = (const float*)d_in[17];
    const float* rb02   = (const float*)d_in[18];
    const float* W_r2   = (const float*)d_in[19];
    const float* rg1    = (const float*)d_in[20];
    const float* rb1    = (const float*)d_in[21];
    const float* W_r3   = (const float*)d_in[22];
    const float* rg2    = (const float*)d_in[23];
    const float* rb2    = (const float*)d_in[24];
    float* out = (float*)d_out;

    const int n = in_sizes[0] / 16;   // 120000

    float *BA, *BB, *BC, *BD, *SUM, *SQ, *SC, *SH;
    int *PA, *PB, *MA, *MB, *HA, *HB, *CTR;
    cudaGetSymbolAddress((void**)&BA,  g_bufA);
    cudaGetSymbolAddress((void**)&BB,  g_bufB);
    cudaGetSymbolAddress((void**)&BC,  g_bufC);
    cudaGetSymbolAddress((void**)&BD,  g_bufD);
    cudaGetSymbolAddress((void**)&SUM, g_sum);
    cudaGetSymbolAddress((void**)&SQ,  g_sq);
    cudaGetSymbolAddress((void**)&SC,  g_sc);
    cudaGetSymbolAddress((void**)&SH,  g_sh);
    cudaGetSymbolAddress((void**)&PA,  g_permA);
    cudaGetSymbolAddress((void**)&PB,  g_permB);
    cudaGetSymbolAddress((void**)&MA,  g_maskA);
    cudaGetSymbolAddress((void**)&MB,  g_maskB);
    cudaGetSymbolAddress((void**)&HA,  g_histA);
    cudaGetSymbolAddress((void**)&HB,  g_histB);
    cudaGetSymbolAddress((void**)&CTR, g_ctr);

    const int TB = 256;
    const int ntiles = (n + TB - 1) / TB;
    const int G = ntiles;

    const int g1632 = persistent_grid<16, 32, 32, false>(ntiles);
    const int g3232f = persistent_grid<32, 32, 32, false>(ntiles);
    const int g3232t = persistent_grid<32, 32, 32, true>(ntiles);
    const int g3264 = persistent_grid<32, 64, 32, false>(ntiles);
    const int g6464 = persistent_grid<64, 64, 32, true>(ntiles);

    // ----- prologue: zero + mask-bucket sort of both rulebooks (4 launches) -----
    zero_kernel<<<2, 512>>>(SUM, SQ, HA, HB, CTR);
    mask_hist_kernel<<<dim3(G, 2), TB>>>(nbr133, nbr313, n, HA, HB, MA, MB);
    scan_kernel<<<2, 512>>>(HA, HB);
    scatter_kernel<<<dim3(G, 2), TB>>>(MA, MB, n, HA, HB, PA, PB);

    // ===== ResContextBlock (16 -> 32) =====
    conv_kernel<16, 32, 32, false><<<dim3(g1632, 1), TB, smem_for(16, 32)>>>(x, nbr133, PA, W_c1, nullptr, nullptr, BA, n, ntiles);
    statsbn_kernel<32><<<148, 512>>>(BA, n, SUM + 0, SQ + 0, g0, b0, SC + 0, SH + 0, CTR + 0);

    conv_kernel<32, 32, 32, true><<<dim3(g3232t, 1), TB, smem_for(32, 32)>>>(BA, nbr313, PB, W_c12, SC + 0, SH + 0, BB, n, ntiles);
    statsbn_kernel<32><<<148, 512>>>(BB, n, SUM + 64, SQ + 64, g02, b02, SC + 64, SH + 64, CTR + 1);

    conv_kernel<16, 32, 32, false><<<dim3(g1632, 1), TB, smem_for(16, 32)>>>(x, nbr313, PB, W_c2, nullptr, nullptr, BC, n, ntiles);
    conv_kernel<32, 32, 32, false><<<dim3(g3232f, 1), TB, smem_for(32, 32)>>>(BC, nbr133, PA, W_c3, nullptr, nullptr, BA, n, ntiles);
    statsbn_kernel<32><<<148, 512>>>(BA, n, SUM + 128, SQ + 128, g2, b2, SC + 128, SH + 128, CTR + 2);

    combine_kernel<32><<<(n * 32 + 255) / 256, 256>>>(BA, SC + 128, SH + 128,
                                                      BB, SC + 64,  SH + 64, BC, n * 32);

    // ===== ResBlock (32 -> 64) =====
    conv_kernel<32, 64, 32, false><<<dim3(g3264, 2), TB, smem_for(32, 32)>>>(BC, nbr313, PB, W_r1, nullptr, nullptr, BA, n, ntiles);
    statsbn_kernel<64><<<148, 512>>>(BA, n, SUM + 192, SQ + 192, rg0, rb0, SC + 192, SH + 192, CTR + 3);

    conv_kernel<64, 64, 32, true><<<dim3(g6464, 2), TB, smem_for(64, 32)>>>(BA, nbr133, PA, W_r12, SC + 192, SH + 192, BB, n, ntiles);
    statsbn_kernel<64><<<148, 512>>>(BB, n, SUM + 256, SQ + 256, rg02, rb02, SC + 256, SH + 256, CTR + 4);

    conv_kernel<32, 64, 32, false><<<dim3(g3264, 2), TB, smem_for(32, 32)>>>(BC, nbr133, PA, W_r2, nullptr, nullptr, BD, n, ntiles);
    statsbn_kernel<64><<<148, 512>>>(BD, n, SUM + 320, SQ + 320, rg1, rb1, SC + 320, SH + 320, CTR + 5);

    conv_kernel<64, 64, 32, true><<<dim3(g6464, 2), TB, smem_for(64, 32)>>>(BD, nbr313, PB, W_r3, SC + 320, SH + 320, BA, n, ntiles);
    statsbn_kernel<64><<<148, 512>>>(BA, n, SUM + 384, SQ + 384, rg2, rb2, SC + 384, SH + 384, CTR + 6);

    combine_kernel<64><<<(n * 64 + 255) / 256, 256>>>(BA, SC + 384, SH + 384,
                                                      BB, SC + 256, SH + 256, out, n * 64);
}